// round 7
// baseline (speedup 1.0000x reference)
#include <cuda_runtime.h>
#include <cuda_fp16.h>
#include <cstdint>

#define ED   128
#define AD   64
#define THREADS 256
#define ROWB 272u        // padded row stride (136 fp16); 8-row ldmatrix tiles are conflict-free

// ---- shared memory layout (bytes) ----
#define A_OFF    0u          // 128 rows x 272 B = 34816
#define W_OFF    34816u      // 64 rows x 272 B = 17408
#define T_OFF    52224u      // 128 f32
#define C_OFF    52736u      // 64 f32
#define W2_OFF   52992u      // 64 f32
#define WARR_OFF 53248u      // 128 f32
#define PART_OFF 53760u      // 256 float2
#define B2_OFF   55808u
#define SMEM_BYTES 55824u

static __device__ __forceinline__ uint32_t smem_u32(const void* p) {
    uint32_t a;
    asm("{ .reg .u64 t; cvta.to.shared.u64 t, %1; cvt.u32.u64 %0, t; }" : "=r"(a) : "l"(p));
    return a;
}

static __device__ __forceinline__ void ldsm_x4(uint32_t r[4], uint32_t addr) {
    asm volatile("ldmatrix.sync.aligned.m8n8.x4.shared.b16 {%0,%1,%2,%3}, [%4];"
        : "=r"(r[0]), "=r"(r[1]), "=r"(r[2]), "=r"(r[3]) : "r"(addr));
}

static __device__ __forceinline__ void mma16816(
    float c[4], const uint32_t a[4], uint32_t b0, uint32_t b1)
{
    asm volatile(
        "mma.sync.aligned.m16n8k16.row.col.f32.f16.f16.f32 "
        "{%0,%1,%2,%3}, {%4,%5,%6,%7}, {%8,%9}, {%0,%1,%2,%3};"
        : "+f"(c[0]), "+f"(c[1]), "+f"(c[2]), "+f"(c[3])
        : "r"(a[0]), "r"(a[1]), "r"(a[2]), "r"(a[3]), "r"(b0), "r"(b1));
}

__global__ void __launch_bounds__(THREADS, 3)
attn_din_kernel(const float* __restrict__ behav,
                const float* __restrict__ target,
                const float* __restrict__ W1,
                const float* __restrict__ b1,
                const float* __restrict__ W2,
                const float* __restrict__ b2,
                float* __restrict__ out)
{
    extern __shared__ char smem[];
    const int tid  = threadIdx.x;
    const int wid  = tid >> 5;
    const int lane = tid & 31;
    const int b    = blockIdx.x;
    const uint32_t su = smem_u32(smem);

    float* tS  = (float*)(smem + T_OFF);
    float* cS  = (float*)(smem + C_OFF);
    float* w2S = (float*)(smem + W2_OFF);
    float* wAr = (float*)(smem + WARR_OFF);

    // ---- stage small vectors ----
    if (tid < ED) tS[tid]  = target[(size_t)b * ED + tid];
    if (tid < AD) w2S[tid] = W2[tid];
    if (tid == 0) *((float*)(smem + B2_OFF)) = b2[0];
    __syncthreads();   // tS ready

    // ---- build per-batch weight W_b[a][k] = Wx + Wd + t[k]*Wm (fp16), once ----
    for (int idx = tid; idx < ED * AD; idx += THREADS) {
        int k = idx >> 6, a = idx & 63;
        float w = W1[k * AD + a] + W1[(384 + k) * AD + a] + tS[k] * W1[(256 + k) * AD + a];
        uint32_t off = (uint32_t)a * ROWB + (uint32_t)k * 2u;
        *reinterpret_cast<__half*>(smem + W_OFF + off) = __float2half_rn(w);
    }

    // ---- c[a] partials: c = b1 + t @ (W_t - W_d), 4 k-quadrants ----
    {
        int a = tid & 63, q = tid >> 6;
        float acc = 0.f;
        for (int kk = 0; kk < 32; kk++) {
            int k = q * 32 + kk;
            acc += tS[k] * (W1[(128 + k) * AD + a] - W1[(384 + k) * AD + a]);
        }
        ((float*)(smem + PART_OFF))[q * 64 + a] = acc;
    }
    __syncthreads();

    if (tid < AD) {
        const float* p = (const float*)(smem + PART_OFF);
        cS[tid] = b1[tid] + p[tid] + p[64 + tid] + p[128 + tid] + p[192 + tid];
    }
    // cS consumed only after the next __syncthreads (inside half loop).

    const int g  = lane >> 2;
    const int t2 = (lane & 3) * 2;

    // ldmatrix per-lane base addresses
    // A x4: lanes 0-15 -> rows (lane&15) of warp's m16 tile, k-byte 0;
    //       lanes 16-31 -> same rows, +16B
    const uint32_t a_base = su + A_OFF
        + (uint32_t)(wid * 16 + (lane & 15)) * ROWB + (uint32_t)((lane >> 4) << 4);
    // B x4 (two n8-tiles per load): lanes 0-7 rows j*16+(lane&7) @k0, 8-15 same rows +16B,
    //       lanes 16-23 rows j*16+8+(lane&7) @k0, 24-31 +16B
    const uint32_t b_base = su + W_OFF
        + (uint32_t)((lane & 7) + ((lane >> 4) << 3)) * ROWB
        + (uint32_t)(((lane >> 3) & 1) << 4);

    float wax = 0.f, way = 0.f;
    const int e2 = tid & 63, q = tid >> 6;

    for (int half = 0; half < 2; half++) {
        const int rows_real = half ? 72 : 128;

        // ---- stage A rows: single fp16 ----
        {
            const float4* bp = (const float4*)(behav
                + ((size_t)b * 200 + (size_t)half * 128) * ED);
            for (int r = wid; r < rows_real; r += 8) {
                float4 v = bp[r * (ED / 4) + lane];
                __half2 h01 = __floats2half2_rn(v.x, v.y);
                __half2 h23 = __floats2half2_rn(v.z, v.w);
                uint32_t off = (uint32_t)r * ROWB + (uint32_t)lane * 8u;
                *reinterpret_cast<uint2*>(smem + A_OFF + off) =
                    make_uint2(*(uint32_t*)&h01, *(uint32_t*)&h23);
            }
        }
        __syncthreads();   // A ready (and cS on half 0)

        // ---- GEMM via ldmatrix: warp w -> rows [16w,16w+16) x [64] ----
        float acc[8][4];
#pragma unroll
        for (int n = 0; n < 8; n++)
#pragma unroll
            for (int i = 0; i < 4; i++) acc[n][i] = 0.f;

        if (wid * 16 < rows_real) {
#pragma unroll
            for (int ks = 0; ks < 8; ks++) {
                const uint32_t ko = (uint32_t)ks * 32u;
                uint32_t a[4];
                ldsm_x4(a, a_base + ko);
#pragma unroll
                for (int j = 0; j < 4; j++) {
                    uint32_t bfr[4];
                    ldsm_x4(bfr, b_base + (uint32_t)j * (16u * ROWB) + ko);
                    mma16816(acc[2 * j],     a, bfr[0], bfr[1]);
                    mma16816(acc[2 * j + 1], a, bfr[2], bfr[3]);
                }
            }
        }

        // ---- epilogue: z = b2 + sum_a relu(D+c)*W2 ; wAr = sigmoid(z) ----
        {
            const float b2v = *((const float*)(smem + B2_OFF));
#pragma unroll
            for (int h = 0; h < 2; h++) {
                float z = 0.f;
#pragma unroll
                for (int n = 0; n < 8; n++) {
                    int col = n * 8 + t2;
                    float h0 = fmaxf(acc[n][2 * h]     + cS[col],     0.f);
                    float h1 = fmaxf(acc[n][2 * h + 1] + cS[col + 1], 0.f);
                    z = fmaf(h0, w2S[col], z);
                    z = fmaf(h1, w2S[col + 1], z);
                }
                z += __shfl_xor_sync(0xFFFFFFFFu, z, 1);
                z += __shfl_xor_sync(0xFFFFFFFFu, z, 2);
                int s = wid * 16 + h * 8 + g;
                if ((lane & 3) == 0) {
                    float wgt = (s < rows_real) ? (1.f / (1.f + __expf(-(z + b2v)))) : 0.f;
                    wAr[s] = wgt;
                }
            }
        }
        __syncthreads();   // wAr ready

        // ---- weighted partial: accumulate w[s]*x[s][e] ----
#pragma unroll 4
        for (int i = 0; i < 32; i++) {
            int s = q * 32 + i;
            uint32_t off = (uint32_t)s * ROWB + (uint32_t)e2 * 4u;
            __half2 h2 = *reinterpret_cast<const __half2*>(smem + A_OFF + off);
            float2 fh = __half22float2(h2);
            float ws = wAr[s];
            wax = fmaf(ws, fh.x, wax);
            way = fmaf(ws, fh.y, way);
        }
        __syncthreads();   // done reading A before restage
    }

    // ---- cross-quadrant reduce and store ----
    ((float2*)(smem + PART_OFF))[q * 64 + e2] = make_float2(wax, way);
    __syncthreads();

    if (tid < 64) {
        const float2* p = (const float2*)(smem + PART_OFF);
        float2 r0 = p[tid], r1 = p[64 + tid], r2 = p[128 + tid], r3 = p[192 + tid];
        float2 o = make_float2(r0.x + r1.x + r2.x + r3.x, r0.y + r1.y + r2.y + r3.y);
        *reinterpret_cast<float2*>(out + (size_t)b * ED + tid * 2) = o;
    }
}

extern "C" void kernel_launch(void* const* d_in, const int* in_sizes, int n_in,
                              void* d_out, int out_size)
{
    const float* behav  = (const float*)d_in[0];
    const float* target = (const float*)d_in[1];
    const float* W1     = (const float*)d_in[2];
    const float* b1     = (const float*)d_in[3];
    const float* W2     = (const float*)d_in[4];
    const float* b2     = (const float*)d_in[5];
    float* out = (float*)d_out;

    const int B = in_sizes[1] / ED;   // 2048

    static bool attr_set = false;
    if (!attr_set) {
        cudaFuncSetAttribute(attn_din_kernel,
                             cudaFuncAttributeMaxDynamicSharedMemorySize, (int)SMEM_BYTES);
        attr_set = true;
    }

    attn_din_kernel<<<B, THREADS, SMEM_BYTES>>>(behav, target, W1, b1, W2, b2, out);
}